// round 4
// baseline (speedup 1.0000x reference)
#include <cuda_runtime.h>
#include <cuda_bf16.h>
#include <math.h>

#define NN 100000
#define EE 3200000

// ---- scratch (device globals; allocation-free) ----
__device__ int    g_deg[NN];
__device__ float  g_dinv[NN];
__device__ int    g_ofs[NN];     // CSR row begin
__device__ int    g_cur[NN];     // fill cursor; == row end after k_fill
__device__ int2   g_edge[EE];    // packed (src, dst)
__device__ int    g_csrc[EE];    // CSR: src ids grouped by dst
__device__ float4 g_y[NN];       // dinv * (x @ W1)
__device__ float4 g_z[NN];       // dinv * (relu(conv1) @ [Wmu|Wls])
__device__ int    g_bsum[512];
__device__ int    g_is64;

// ---- init: zero deg; thread 0 also detects int64 vs int32 edge_index ----
__global__ void k_init(const unsigned int* __restrict__ ei, int n) {
    int i = blockIdx.x * blockDim.x + threadIdx.x;
    if (i < n) g_deg[i] = 0;
    if (blockIdx.x == 0 && threadIdx.x == 0) {
        int all0 = 1;
        #pragma unroll 1
        for (int k = 0; k < 64; ++k)
            if (ei[2 * k + 1] != 0u) { all0 = 0; break; }
        g_is64 = all0;   // int64 little-endian, ids < 2^31 => odd words all 0
    }
}

// ---- decode edges to packed int2 + degree histogram ----
__global__ void k_edges(const void* __restrict__ ei, int e) {
    int i = blockIdx.x * blockDim.x + threadIdx.x;
    if (i >= e) return;
    int s, d;
    if (g_is64) {
        const long long* p = (const long long*)ei;
        s = (int)__ldg(&p[i]);
        d = (int)__ldg(&p[(long long)e + i]);
    } else {
        const int* p = (const int*)ei;
        s = __ldg(&p[i]);
        d = __ldg(&p[e + i]);
    }
    g_edge[i] = make_int2(s, d);
    atomicAdd(&g_deg[d], 1);
}

// ---- 3-stage exclusive scan of g_deg -> g_ofs (+ dinv fused in stage 3) ----
__global__ void k_scan1(int n) {
    int i = blockIdx.x * 256 + threadIdx.x;
    int v = (i < n) ? g_deg[i] : 0;
    #pragma unroll
    for (int o = 16; o; o >>= 1) v += __shfl_xor_sync(0xffffffffu, v, o);
    __shared__ int ws[8];
    if ((threadIdx.x & 31) == 0) ws[threadIdx.x >> 5] = v;
    __syncthreads();
    if (threadIdx.x == 0) {
        int s = 0;
        #pragma unroll
        for (int k = 0; k < 8; ++k) s += ws[k];
        g_bsum[blockIdx.x] = s;
    }
}

__global__ void k_scan2(int nb) {
    __shared__ int s[512];
    int t = threadIdx.x;
    int orig = (t < nb) ? g_bsum[t] : 0;
    s[t] = orig;
    __syncthreads();
    for (int off = 1; off < 512; off <<= 1) {
        int v = (t >= off) ? s[t - off] : 0;
        __syncthreads();
        s[t] += v;
        __syncthreads();
    }
    if (t < nb) g_bsum[t] = s[t] - orig;   // exclusive block offsets
}

__global__ void k_scan3(int n) {
    int i = blockIdx.x * 256 + threadIdx.x;
    int warp = threadIdx.x >> 5, lane = threadIdx.x & 31;
    int v = (i < n) ? g_deg[i] : 0;
    int x = v;
    #pragma unroll
    for (int o = 1; o < 32; o <<= 1) {
        int t = __shfl_up_sync(0xffffffffu, x, o);
        if (lane >= o) x += t;
    }
    __shared__ int ws[8], wofs[8];
    if (lane == 31) ws[warp] = x;
    __syncthreads();
    if (threadIdx.x == 0) {
        int run = 0;
        #pragma unroll
        for (int k = 0; k < 8; ++k) { wofs[k] = run; run += ws[k]; }
    }
    __syncthreads();
    if (i < n) {
        int e0 = x - v + wofs[warp] + g_bsum[blockIdx.x];
        g_ofs[i] = e0;
        g_cur[i] = e0;
        g_dinv[i] = rsqrtf((float)(v + 1));   // +1 self loop
    }
}

// ---- CSR fill: place src ids into per-dst slots ----
__global__ void k_fill(int e) {
    int i = blockIdx.x * blockDim.x + threadIdx.x;
    if (i >= e) return;
    int2 ed = g_edge[i];
    int pos = atomicAdd(&g_cur[ed.y], 1);
    g_csrc[pos] = ed.x;
}

// ---- y = dinv * (x @ W1): one warp per row, HBM-bound ----
__global__ void __launch_bounds__(256) k_gemm(const float* __restrict__ x,
                                              const float* __restrict__ W1, int n) {
    __shared__ float4 Ws[512];
    int t = threadIdx.x;
    const float4* W4 = (const float4*)W1;
    Ws[t]       = W4[t];
    Ws[t + 256] = W4[t + 256];
    __syncthreads();

    int warp = t >> 5, lane = t & 31;
    int row  = blockIdx.x * 8 + warp;
    if (row >= n) return;

    const float4* xr = (const float4*)(x + (size_t)row * 512);
    float4 acc = make_float4(0.f, 0.f, 0.f, 0.f);
    #pragma unroll
    for (int i = 0; i < 4; ++i) {
        float4 xv = __ldg(&xr[i * 32 + lane]);
        int k = i * 128 + lane * 4;
        float4 w0 = Ws[k], w1 = Ws[k + 1], w2 = Ws[k + 2], w3 = Ws[k + 3];
        acc.x += xv.x * w0.x + xv.y * w1.x + xv.z * w2.x + xv.w * w3.x;
        acc.y += xv.x * w0.y + xv.y * w1.y + xv.z * w2.y + xv.w * w3.y;
        acc.z += xv.x * w0.z + xv.y * w1.z + xv.z * w2.z + xv.w * w3.z;
        acc.w += xv.x * w0.w + xv.y * w1.w + xv.z * w2.w + xv.w * w3.w;
    }
    #pragma unroll
    for (int off = 16; off; off >>= 1) {
        acc.x += __shfl_xor_sync(0xffffffffu, acc.x, off);
        acc.y += __shfl_xor_sync(0xffffffffu, acc.y, off);
        acc.z += __shfl_xor_sync(0xffffffffu, acc.z, off);
        acc.w += __shfl_xor_sync(0xffffffffu, acc.w, off);
    }
    if (lane == 0) {
        float di = g_dinv[row];
        g_y[row] = make_float4(di * acc.x, di * acc.y, di * acc.z, di * acc.w);
    }
}

// ---- conv1 gather (warp/node): 1 random 16B load per edge, no atomics ----
__global__ void __launch_bounds__(256) k_conv1(const float* __restrict__ b1,
                                               const float* __restrict__ Wmu,
                                               const float* __restrict__ Wls, int n) {
    int warp = threadIdx.x >> 5, lane = threadIdx.x & 31;
    int node = blockIdx.x * 8 + warp;
    if (node >= n) return;
    int beg = g_ofs[node], end = g_cur[node];
    float4 acc = make_float4(0.f, 0.f, 0.f, 0.f);
    for (int j = beg + lane; j < end; j += 32) {
        float4 v = g_y[__ldg(&g_csrc[j])];
        acc.x += v.x; acc.y += v.y; acc.z += v.z; acc.w += v.w;
    }
    #pragma unroll
    for (int o = 16; o; o >>= 1) {
        acc.x += __shfl_xor_sync(0xffffffffu, acc.x, o);
        acc.y += __shfl_xor_sync(0xffffffffu, acc.y, o);
        acc.z += __shfl_xor_sync(0xffffffffu, acc.z, o);
        acc.w += __shfl_xor_sync(0xffffffffu, acc.w, o);
    }
    if (lane == 0) {
        float di = g_dinv[node];
        float4 y = g_y[node];
        float h0 = fmaxf(di * (acc.x + y.x) + __ldg(&b1[0]), 0.f);
        float h1 = fmaxf(di * (acc.y + y.y) + __ldg(&b1[1]), 0.f);
        float h2 = fmaxf(di * (acc.z + y.z) + __ldg(&b1[2]), 0.f);
        float h3 = fmaxf(di * (acc.w + y.w) + __ldg(&b1[3]), 0.f);
        float4 o;   // W_mu, W_ls: [4,2] row-major
        o.x = h0 * __ldg(&Wmu[0]) + h1 * __ldg(&Wmu[2]) + h2 * __ldg(&Wmu[4]) + h3 * __ldg(&Wmu[6]);
        o.y = h0 * __ldg(&Wmu[1]) + h1 * __ldg(&Wmu[3]) + h2 * __ldg(&Wmu[5]) + h3 * __ldg(&Wmu[7]);
        o.z = h0 * __ldg(&Wls[0]) + h1 * __ldg(&Wls[2]) + h2 * __ldg(&Wls[4]) + h3 * __ldg(&Wls[6]);
        o.w = h0 * __ldg(&Wls[1]) + h1 * __ldg(&Wls[3]) + h2 * __ldg(&Wls[5]) + h3 * __ldg(&Wls[7]);
        g_z[node] = make_float4(di * o.x, di * o.y, di * o.z, di * o.w);
    }
}

// ---- conv2 gather (warp/node) + fused bias + output store ----
__global__ void __launch_bounds__(256) k_conv2(const float* __restrict__ bmu,
                                               const float* __restrict__ bls,
                                               float* __restrict__ out, int n) {
    int warp = threadIdx.x >> 5, lane = threadIdx.x & 31;
    int node = blockIdx.x * 8 + warp;
    if (node >= n) return;
    int beg = g_ofs[node], end = g_cur[node];
    float4 acc = make_float4(0.f, 0.f, 0.f, 0.f);
    for (int j = beg + lane; j < end; j += 32) {
        float4 v = g_z[__ldg(&g_csrc[j])];
        acc.x += v.x; acc.y += v.y; acc.z += v.z; acc.w += v.w;
    }
    #pragma unroll
    for (int o = 16; o; o >>= 1) {
        acc.x += __shfl_xor_sync(0xffffffffu, acc.x, o);
        acc.y += __shfl_xor_sync(0xffffffffu, acc.y, o);
        acc.z += __shfl_xor_sync(0xffffffffu, acc.z, o);
        acc.w += __shfl_xor_sync(0xffffffffu, acc.w, o);
    }
    if (lane == 0) {
        float di = g_dinv[node];
        float4 z = g_z[node];
        float2 mu, ls;
        mu.x = di * (acc.x + z.x) + __ldg(&bmu[0]);
        mu.y = di * (acc.y + z.y) + __ldg(&bmu[1]);
        ls.x = di * (acc.z + z.z) + __ldg(&bls[0]);
        ls.y = di * (acc.w + z.w) + __ldg(&bls[1]);
        ((float2*)out)[node] = mu;                       // mu [N,2]
        ((float2*)(out + 2 * (size_t)n))[node] = ls;     // logstd [N,2]
    }
}

extern "C" void kernel_launch(void* const* d_in, const int* in_sizes, int n_in,
                              void* d_out, int out_size) {
    const float* x   = (const float*)d_in[0];
    const void*  ei  = d_in[1];
    const float* W1  = (const float*)d_in[2];
    const float* b1  = (const float*)d_in[3];
    const float* Wmu = (const float*)d_in[4];
    const float* bmu = (const float*)d_in[5];
    const float* Wls = (const float*)d_in[6];
    const float* bls = (const float*)d_in[7];

    int n = in_sizes[0] / 512;   // 100000
    int e = in_sizes[1] / 2;     // 3200000

    int nb = (n + 255) / 256;
    int eb = (e + 255) / 256;

    k_init<<<nb, 256>>>((const unsigned int*)ei, n);
    k_edges<<<eb, 256>>>(ei, e);
    k_scan1<<<nb, 256>>>(n);
    k_scan2<<<1, 512>>>(nb);
    k_scan3<<<nb, 256>>>(n);
    k_fill<<<eb, 256>>>(e);
    k_gemm<<<(n + 7) / 8, 256>>>(x, W1, n);
    k_conv1<<<(n + 7) / 8, 256>>>(b1, Wmu, Wls, n);
    k_conv2<<<(n + 7) / 8, 256>>>(bmu, bls, (float*)d_out, n);
}

// round 5
// speedup vs baseline: 1.0058x; 1.0058x over previous
#include <cuda_runtime.h>
#include <cuda_bf16.h>
#include <math.h>

#define NN 100000
#define EE 3200000

// ---- scratch (device globals; allocation-free) ----
__device__ int    g_odeg[NN];    // out-degree (src histogram) -> CSR-by-src
__device__ int    g_deg[NN];     // in-degree (dst histogram)  -> dinv
__device__ float  g_dinv[NN];
__device__ int    g_ofs[NN];     // CSR row begin (scan of odeg)
__device__ int    g_cur[NN];     // fill cursor; == row end after k_fill
__device__ int    g_cdst[EE];    // dst ids grouped by src
__device__ float4 g_xw[NN];      // raw x @ W1
__device__ float4 g_z[NN];       // dinv * (relu(conv1) @ [Wmu|Wls])
__device__ float4 g_acc1[NN];
__device__ float4 g_acc2[NN];
__device__ int    g_bsum[512];
__device__ int    g_is64;

__device__ __forceinline__ void decode_edge(const void* ei, int e, int i,
                                            int& s, int& d) {
    if (g_is64) {
        const long long* p = (const long long*)ei;
        s = (int)__ldg(&p[i]);
        d = (int)__ldg(&p[(long long)e + i]);
    } else {
        const int* p = (const int*)ei;
        s = __ldg(&p[i]);
        d = __ldg(&p[e + i]);
    }
}

// ---- init: zero histograms + accumulators; thread 0 detects int64/int32 ----
__global__ void k_init(const unsigned int* __restrict__ ei, int n) {
    int i = blockIdx.x * blockDim.x + threadIdx.x;
    if (i < n) {
        g_odeg[i] = 0;
        g_deg[i]  = 0;
        g_acc1[i] = make_float4(0.f, 0.f, 0.f, 0.f);
        g_acc2[i] = make_float4(0.f, 0.f, 0.f, 0.f);
    }
    if (blockIdx.x == 0 && threadIdx.x == 0) {
        int all0 = 1;
        #pragma unroll 1
        for (int k = 0; k < 64; ++k)
            if (ei[2 * k + 1] != 0u) { all0 = 0; break; }
        g_is64 = all0;   // int64 LE with ids < 2^31 => odd words all zero
    }
}

// ---- histograms: out-degree over src, in-degree over dst ----
__global__ void k_edges(const void* __restrict__ ei, int e) {
    int i = blockIdx.x * blockDim.x + threadIdx.x;
    if (i >= e) return;
    int s, d;
    decode_edge(ei, e, i, s, d);
    atomicAdd(&g_odeg[s], 1);
    atomicAdd(&g_deg[d], 1);
}

// ---- 3-stage exclusive scan of g_odeg -> g_ofs (+ dinv from g_deg fused) ----
__global__ void k_scan1(int n) {
    int i = blockIdx.x * 256 + threadIdx.x;
    int v = (i < n) ? g_odeg[i] : 0;
    #pragma unroll
    for (int o = 16; o; o >>= 1) v += __shfl_xor_sync(0xffffffffu, v, o);
    __shared__ int ws[8];
    if ((threadIdx.x & 31) == 0) ws[threadIdx.x >> 5] = v;
    __syncthreads();
    if (threadIdx.x == 0) {
        int s = 0;
        #pragma unroll
        for (int k = 0; k < 8; ++k) s += ws[k];
        g_bsum[blockIdx.x] = s;
    }
}

__global__ void k_scan2(int nb) {
    __shared__ int s[512];
    int t = threadIdx.x;
    int orig = (t < nb) ? g_bsum[t] : 0;
    s[t] = orig;
    __syncthreads();
    for (int off = 1; off < 512; off <<= 1) {
        int v = (t >= off) ? s[t - off] : 0;
        __syncthreads();
        s[t] += v;
        __syncthreads();
    }
    if (t < nb) g_bsum[t] = s[t] - orig;   // exclusive block offsets
}

__global__ void k_scan3(int n) {
    int i = blockIdx.x * 256 + threadIdx.x;
    int warp = threadIdx.x >> 5, lane = threadIdx.x & 31;
    int v = (i < n) ? g_odeg[i] : 0;
    int x = v;
    #pragma unroll
    for (int o = 1; o < 32; o <<= 1) {
        int t = __shfl_up_sync(0xffffffffu, x, o);
        if (lane >= o) x += t;
    }
    __shared__ int ws[8], wofs[8];
    if (lane == 31) ws[warp] = x;
    __syncthreads();
    if (threadIdx.x == 0) {
        int run = 0;
        #pragma unroll
        for (int k = 0; k < 8; ++k) { wofs[k] = run; run += ws[k]; }
    }
    __syncthreads();
    if (i < n) {
        int e0 = x - v + wofs[warp] + g_bsum[blockIdx.x];
        g_ofs[i] = e0;
        g_cur[i] = e0;
        g_dinv[i] = rsqrtf((float)(g_deg[i] + 1));   // in-degree + self loop
    }
}

// ---- CSR fill: re-decode (edge_index is L2-resident now), group dst by src ----
__global__ void k_fill(const void* __restrict__ ei, int e) {
    int i = blockIdx.x * blockDim.x + threadIdx.x;
    if (i >= e) return;
    int s, d;
    decode_edge(ei, e, i, s, d);
    int pos = atomicAdd(&g_cur[s], 1);
    g_cdst[pos] = d;
}

// ---- xw = x @ W1 (raw): one warp per row, HBM-bound; runs on side stream ----
__global__ void __launch_bounds__(256) k_gemm(const float* __restrict__ x,
                                              const float* __restrict__ W1, int n) {
    __shared__ float4 Ws[512];
    int t = threadIdx.x;
    const float4* W4 = (const float4*)W1;
    Ws[t]       = W4[t];
    Ws[t + 256] = W4[t + 256];
    __syncthreads();

    int warp = t >> 5, lane = t & 31;
    int row  = blockIdx.x * 8 + warp;
    if (row >= n) return;

    const float4* xr = (const float4*)(x + (size_t)row * 512);
    float4 acc = make_float4(0.f, 0.f, 0.f, 0.f);
    #pragma unroll
    for (int i = 0; i < 4; ++i) {
        float4 xv = __ldg(&xr[i * 32 + lane]);
        int k = i * 128 + lane * 4;
        float4 w0 = Ws[k], w1 = Ws[k + 1], w2 = Ws[k + 2], w3 = Ws[k + 3];
        acc.x += xv.x * w0.x + xv.y * w1.x + xv.z * w2.x + xv.w * w3.x;
        acc.y += xv.x * w0.y + xv.y * w1.y + xv.z * w2.y + xv.w * w3.y;
        acc.z += xv.x * w0.z + xv.y * w1.z + xv.z * w2.z + xv.w * w3.z;
        acc.w += xv.x * w0.w + xv.y * w1.w + xv.z * w2.w + xv.w * w3.w;
    }
    #pragma unroll
    for (int off = 16; off; off >>= 1) {
        acc.x += __shfl_xor_sync(0xffffffffu, acc.x, off);
        acc.y += __shfl_xor_sync(0xffffffffu, acc.y, off);
        acc.z += __shfl_xor_sync(0xffffffffu, acc.z, off);
        acc.w += __shfl_xor_sync(0xffffffffu, acc.w, off);
    }
    if (lane == 0) g_xw[row] = acc;
}

// ---- conv1: warp per SRC node; value loaded once, 1 random RED per edge ----
__global__ void __launch_bounds__(256) k_conv1(int n) {
    int warp = threadIdx.x >> 5, lane = threadIdx.x & 31;
    int node = blockIdx.x * 8 + warp;
    if (node >= n) return;
    int beg = g_ofs[node], end = g_cur[node];
    if (beg == end) return;
    float di = g_dinv[node];           // broadcast loads (1 line each)
    float4 xv = g_xw[node];
    float4 v = make_float4(di * xv.x, di * xv.y, di * xv.z, di * xv.w);
    for (int j = beg + lane; j < end; j += 32)
        atomicAdd(&g_acc1[__ldg(&g_cdst[j])], v);
}

// ---- finalize conv1: h = relu(di*(acc+di*xw)+b1); z = di * (h @ [Wmu|Wls]) ----
__global__ void k_fin1(const float* __restrict__ b1,
                       const float* __restrict__ Wmu,
                       const float* __restrict__ Wls, int n) {
    int i = blockIdx.x * blockDim.x + threadIdx.x;
    if (i >= n) return;
    float di = g_dinv[i];
    float4 a  = g_acc1[i];
    float4 xv = g_xw[i];
    float h0 = fmaxf(di * (a.x + di * xv.x) + __ldg(&b1[0]), 0.f);
    float h1 = fmaxf(di * (a.y + di * xv.y) + __ldg(&b1[1]), 0.f);
    float h2 = fmaxf(di * (a.z + di * xv.z) + __ldg(&b1[2]), 0.f);
    float h3 = fmaxf(di * (a.w + di * xv.w) + __ldg(&b1[3]), 0.f);
    float4 o;   // W_mu, W_ls: [4,2] row-major
    o.x = h0 * __ldg(&Wmu[0]) + h1 * __ldg(&Wmu[2]) + h2 * __ldg(&Wmu[4]) + h3 * __ldg(&Wmu[6]);
    o.y = h0 * __ldg(&Wmu[1]) + h1 * __ldg(&Wmu[3]) + h2 * __ldg(&Wmu[5]) + h3 * __ldg(&Wmu[7]);
    o.z = h0 * __ldg(&Wls[0]) + h1 * __ldg(&Wls[2]) + h2 * __ldg(&Wls[4]) + h3 * __ldg(&Wls[6]);
    o.w = h0 * __ldg(&Wls[1]) + h1 * __ldg(&Wls[3]) + h2 * __ldg(&Wls[5]) + h3 * __ldg(&Wls[7]);
    g_z[i] = make_float4(di * o.x, di * o.y, di * o.z, di * o.w);
}

// ---- conv2: warp per SRC node, scatter z ----
__global__ void __launch_bounds__(256) k_conv2(int n) {
    int warp = threadIdx.x >> 5, lane = threadIdx.x & 31;
    int node = blockIdx.x * 8 + warp;
    if (node >= n) return;
    int beg = g_ofs[node], end = g_cur[node];
    if (beg == end) return;
    float4 v = g_z[node];
    for (int j = beg + lane; j < end; j += 32)
        atomicAdd(&g_acc2[__ldg(&g_cdst[j])], v);
}

// ---- finalize conv2: out = di*(acc2 + z) + bias ----
__global__ void k_fin2(const float* __restrict__ bmu,
                       const float* __restrict__ bls,
                       float* __restrict__ out, int n) {
    int i = blockIdx.x * blockDim.x + threadIdx.x;
    if (i >= n) return;
    float di = g_dinv[i];
    float4 a = g_acc2[i];
    float4 z = g_z[i];
    float2 mu, ls;
    mu.x = di * (a.x + z.x) + __ldg(&bmu[0]);
    mu.y = di * (a.y + z.y) + __ldg(&bmu[1]);
    ls.x = di * (a.z + z.z) + __ldg(&bls[0]);
    ls.y = di * (a.w + z.w) + __ldg(&bls[1]);
    ((float2*)out)[i] = mu;                       // mu [N,2]
    ((float2*)(out + 2 * (size_t)n))[i] = ls;     // logstd [N,2]
}

extern "C" void kernel_launch(void* const* d_in, const int* in_sizes, int n_in,
                              void* d_out, int out_size) {
    const float* x   = (const float*)d_in[0];
    const void*  ei  = d_in[1];
    const float* W1  = (const float*)d_in[2];
    const float* b1  = (const float*)d_in[3];
    const float* Wmu = (const float*)d_in[4];
    const float* bmu = (const float*)d_in[5];
    const float* Wls = (const float*)d_in[6];
    const float* bls = (const float*)d_in[7];

    int n = in_sizes[0] / 512;   // 100000
    int e = in_sizes[1] / 2;     // 3200000

    int nb = (n + 255) / 256;
    int eb = (e + 255) / 256;

    // Fork a side stream for the independent HBM-bound GEMM (capture-safe
    // fork/join via events; objects are intentionally not destroyed —
    // kernel_launch runs only for correctness + capture).
    cudaStream_t s2;
    cudaEvent_t ev0, ev1;
    cudaStreamCreateWithFlags(&s2, cudaStreamNonBlocking);
    cudaEventCreateWithFlags(&ev0, cudaEventDisableTiming);
    cudaEventCreateWithFlags(&ev1, cudaEventDisableTiming);

    cudaEventRecord(ev0, 0);
    cudaStreamWaitEvent(s2, ev0, 0);
    k_gemm<<<(n + 7) / 8, 256, 0, s2>>>(x, W1, n);
    cudaEventRecord(ev1, s2);

    // Edge pipeline on the main stream, overlapped with gemm.
    k_init<<<nb, 256>>>((const unsigned int*)ei, n);
    k_edges<<<eb, 256>>>(ei, e);
    k_scan1<<<nb, 256>>>(n);
    k_scan2<<<1, 512>>>(nb);
    k_scan3<<<nb, 256>>>(n);
    k_fill<<<eb, 256>>>(ei, e);

    cudaStreamWaitEvent(0, ev1, 0);   // join gemm before conv1
    k_conv1<<<(n + 7) / 8, 256>>>(n);
    k_fin1<<<nb, 256>>>(b1, Wmu, Wls, n);
    k_conv2<<<(n + 7) / 8, 256>>>(n);
    k_fin2<<<nb, 256>>>(bmu, bls, (float*)d_out, n);
}

// round 6
// speedup vs baseline: 1.2287x; 1.2216x over previous
#include <cuda_runtime.h>
#include <cuda_bf16.h>
#include <math.h>

#define NN 100000
#define EE 3200000

// ---- scratch (device globals; allocation-free) ----
__device__ int    g_deg[NN];
__device__ float  g_dinv[NN];
__device__ int2   g_edge[EE];    // packed (src, dst)
__device__ float4 g_xw[NN];      // raw x @ W1
__device__ float4 g_y[NN];       // dinv * xw
__device__ float4 g_z[NN];       // dinv * (relu(conv1) @ [Wmu|Wls])
__device__ float4 g_acc1[NN];
__device__ float4 g_acc2[NN];
__device__ int    g_is64;

// ---- init: zero deg + accumulators; thread 0 detects int64 vs int32 ----
__global__ void k_init(const unsigned int* __restrict__ ei, int n) {
    int i = blockIdx.x * blockDim.x + threadIdx.x;
    if (i < n) {
        g_deg[i]  = 0;
        g_acc1[i] = make_float4(0.f, 0.f, 0.f, 0.f);
        g_acc2[i] = make_float4(0.f, 0.f, 0.f, 0.f);
    }
    if (blockIdx.x == 0 && threadIdx.x == 0) {
        int all0 = 1;
        #pragma unroll 1
        for (int k = 0; k < 64; ++k)
            if (ei[2 * k + 1] != 0u) { all0 = 0; break; }
        g_is64 = all0;   // int64 LE with ids < 2^31 => odd words all zero
    }
}

// ---- decode 2 edges/thread to packed int2 + degree histogram ----
__global__ void k_edges(const void* __restrict__ ei, int e) {
    int i = blockIdx.x * blockDim.x + threadIdx.x;
    int npair = e >> 1;
    if (i < npair) {
        int s0, s1, d0, d1;
        if (g_is64) {
            const longlong2* ps = (const longlong2*)ei;
            const longlong2* pd = (const longlong2*)((const long long*)ei + e);
            longlong2 sv = __ldg(&ps[i]);
            longlong2 dv = __ldg(&pd[i]);
            s0 = (int)sv.x; s1 = (int)sv.y; d0 = (int)dv.x; d1 = (int)dv.y;
        } else {
            const int2* ps = (const int2*)ei;
            const int2* pd = (const int2*)((const int*)ei + e);
            int2 sv = __ldg(&ps[i]);
            int2 dv = __ldg(&pd[i]);
            s0 = sv.x; s1 = sv.y; d0 = dv.x; d1 = dv.y;
        }
        ((int4*)g_edge)[i] = make_int4(s0, d0, s1, d1);
        atomicAdd(&g_deg[d0], 1);
        atomicAdd(&g_deg[d1], 1);
    }
    if (i == 0 && (e & 1)) {           // odd tail (E even in practice)
        int s, d;
        if (g_is64) {
            const long long* p = (const long long*)ei;
            s = (int)p[e - 1]; d = (int)p[2 * (long long)e - 1];
        } else {
            const int* p = (const int*)ei;
            s = p[e - 1]; d = p[2 * e - 1];
        }
        g_edge[e - 1] = make_int2(s, d);
        atomicAdd(&g_deg[d], 1);
    }
}

// ---- xw = x @ W1 (raw): one warp per row, HBM-bound; runs on side stream ----
__global__ void __launch_bounds__(256) k_gemm(const float* __restrict__ x,
                                              const float* __restrict__ W1, int n) {
    __shared__ float4 Ws[512];
    int t = threadIdx.x;
    const float4* W4 = (const float4*)W1;
    Ws[t]       = W4[t];
    Ws[t + 256] = W4[t + 256];
    __syncthreads();

    int warp = t >> 5, lane = t & 31;
    int row  = blockIdx.x * 8 + warp;
    if (row >= n) return;

    const float4* xr = (const float4*)(x + (size_t)row * 512);
    float4 acc = make_float4(0.f, 0.f, 0.f, 0.f);
    #pragma unroll
    for (int i = 0; i < 4; ++i) {
        float4 xv = __ldg(&xr[i * 32 + lane]);
        int k = i * 128 + lane * 4;
        float4 w0 = Ws[k], w1 = Ws[k + 1], w2 = Ws[k + 2], w3 = Ws[k + 3];
        acc.x += xv.x * w0.x + xv.y * w1.x + xv.z * w2.x + xv.w * w3.x;
        acc.y += xv.x * w0.y + xv.y * w1.y + xv.z * w2.y + xv.w * w3.y;
        acc.z += xv.x * w0.z + xv.y * w1.z + xv.z * w2.z + xv.w * w3.z;
        acc.w += xv.x * w0.w + xv.y * w1.w + xv.z * w2.w + xv.w * w3.w;
    }
    #pragma unroll
    for (int off = 16; off; off >>= 1) {
        acc.x += __shfl_xor_sync(0xffffffffu, acc.x, off);
        acc.y += __shfl_xor_sync(0xffffffffu, acc.y, off);
        acc.z += __shfl_xor_sync(0xffffffffu, acc.z, off);
        acc.w += __shfl_xor_sync(0xffffffffu, acc.w, off);
    }
    if (lane == 0) g_xw[row] = acc;
}

// ---- after join: dinv = rsqrt(deg+1); y = dinv * xw ----
__global__ void k_y(int n) {
    int i = blockIdx.x * blockDim.x + threadIdx.x;
    if (i >= n) return;
    float di = rsqrtf((float)(g_deg[i] + 1));
    g_dinv[i] = di;
    float4 v = g_xw[i];
    g_y[i] = make_float4(di * v.x, di * v.y, di * v.z, di * v.w);
}

// ---- conv1 scatter: 4 edges/thread, 4 independent gathers + 4 REDs ----
__global__ void __launch_bounds__(256) k_conv1(int e) {
    int i = blockIdx.x * blockDim.x + threadIdx.x;
    int base = i * 4;
    if (base >= e) return;
    if (base + 3 < e) {
        int4 a = ((const int4*)g_edge)[i * 2];
        int4 b = ((const int4*)g_edge)[i * 2 + 1];
        float4 v0 = g_y[a.x];
        float4 v1 = g_y[a.z];
        float4 v2 = g_y[b.x];
        float4 v3 = g_y[b.z];
        atomicAdd(&g_acc1[a.y], v0);
        atomicAdd(&g_acc1[a.w], v1);
        atomicAdd(&g_acc1[b.y], v2);
        atomicAdd(&g_acc1[b.w], v3);
    } else {
        for (int j = base; j < e; ++j) {
            int2 ed = g_edge[j];
            atomicAdd(&g_acc1[ed.y], g_y[ed.x]);
        }
    }
}

// ---- finalize conv1: h = relu(di*(acc+y)+b1); z = di * (h @ [Wmu|Wls]) ----
__global__ void k_fin1(const float* __restrict__ b1,
                       const float* __restrict__ Wmu,
                       const float* __restrict__ Wls, int n) {
    int i = blockIdx.x * blockDim.x + threadIdx.x;
    if (i >= n) return;
    float di = g_dinv[i];
    float4 a = g_acc1[i];
    float4 y = g_y[i];
    float h0 = fmaxf(di * (a.x + y.x) + __ldg(&b1[0]), 0.f);
    float h1 = fmaxf(di * (a.y + y.y) + __ldg(&b1[1]), 0.f);
    float h2 = fmaxf(di * (a.z + y.z) + __ldg(&b1[2]), 0.f);
    float h3 = fmaxf(di * (a.w + y.w) + __ldg(&b1[3]), 0.f);
    float4 o;   // W_mu, W_ls: [4,2] row-major
    o.x = h0 * __ldg(&Wmu[0]) + h1 * __ldg(&Wmu[2]) + h2 * __ldg(&Wmu[4]) + h3 * __ldg(&Wmu[6]);
    o.y = h0 * __ldg(&Wmu[1]) + h1 * __ldg(&Wmu[3]) + h2 * __ldg(&Wmu[5]) + h3 * __ldg(&Wmu[7]);
    o.z = h0 * __ldg(&Wls[0]) + h1 * __ldg(&Wls[2]) + h2 * __ldg(&Wls[4]) + h3 * __ldg(&Wls[6]);
    o.w = h0 * __ldg(&Wls[1]) + h1 * __ldg(&Wls[3]) + h2 * __ldg(&Wls[5]) + h3 * __ldg(&Wls[7]);
    g_z[i] = make_float4(di * o.x, di * o.y, di * o.z, di * o.w);
}

// ---- conv2 scatter: 4 edges/thread ----
__global__ void __launch_bounds__(256) k_conv2(int e) {
    int i = blockIdx.x * blockDim.x + threadIdx.x;
    int base = i * 4;
    if (base >= e) return;
    if (base + 3 < e) {
        int4 a = ((const int4*)g_edge)[i * 2];
        int4 b = ((const int4*)g_edge)[i * 2 + 1];
        float4 v0 = g_z[a.x];
        float4 v1 = g_z[a.z];
        float4 v2 = g_z[b.x];
        float4 v3 = g_z[b.z];
        atomicAdd(&g_acc2[a.y], v0);
        atomicAdd(&g_acc2[a.w], v1);
        atomicAdd(&g_acc2[b.y], v2);
        atomicAdd(&g_acc2[b.w], v3);
    } else {
        for (int j = base; j < e; ++j) {
            int2 ed = g_edge[j];
            atomicAdd(&g_acc2[ed.y], g_z[ed.x]);
        }
    }
}

// ---- finalize conv2: out = di*(acc2+z) + bias ----
__global__ void k_fin2(const float* __restrict__ bmu,
                       const float* __restrict__ bls,
                       float* __restrict__ out, int n) {
    int i = blockIdx.x * blockDim.x + threadIdx.x;
    if (i >= n) return;
    float di = g_dinv[i];
    float4 a = g_acc2[i];
    float4 z = g_z[i];
    float2 mu, ls;
    mu.x = di * (a.x + z.x) + __ldg(&bmu[0]);
    mu.y = di * (a.y + z.y) + __ldg(&bmu[1]);
    ls.x = di * (a.z + z.z) + __ldg(&bls[0]);
    ls.y = di * (a.w + z.w) + __ldg(&bls[1]);
    ((float2*)out)[i] = mu;                       // mu [N,2]
    ((float2*)(out + 2 * (size_t)n))[i] = ls;     // logstd [N,2]
}

extern "C" void kernel_launch(void* const* d_in, const int* in_sizes, int n_in,
                              void* d_out, int out_size) {
    const float* x   = (const float*)d_in[0];
    const void*  ei  = d_in[1];
    const float* W1  = (const float*)d_in[2];
    const float* b1  = (const float*)d_in[3];
    const float* Wmu = (const float*)d_in[4];
    const float* bmu = (const float*)d_in[5];
    const float* Wls = (const float*)d_in[6];
    const float* bls = (const float*)d_in[7];

    int n = in_sizes[0] / 512;   // 100000
    int e = in_sizes[1] / 2;     // 3200000

    int nb = (n + 255) / 256;
    int pb = ((e >> 1) + 255) / 256;      // edge-pair blocks
    int qb = ((e + 3) / 4 + 255) / 256;   // edge-quad blocks

    // Side stream for the independent HBM-bound GEMM (capture-safe fork/join).
    cudaStream_t s2;
    cudaEvent_t ev0, ev1;
    cudaStreamCreateWithFlags(&s2, cudaStreamNonBlocking);
    cudaEventCreateWithFlags(&ev0, cudaEventDisableTiming);
    cudaEventCreateWithFlags(&ev1, cudaEventDisableTiming);

    cudaEventRecord(ev0, 0);
    cudaStreamWaitEvent(s2, ev0, 0);
    k_gemm<<<(n + 7) / 8, 256, 0, s2>>>(x, W1, n);   // raw xw (no dinv dep)
    cudaEventRecord(ev1, s2);

    // Edge pipeline on the main stream, overlapped with gemm.
    k_init<<<nb, 256>>>((const unsigned int*)ei, n);
    k_edges<<<pb, 256>>>(ei, e);

    cudaStreamWaitEvent(0, ev1, 0);   // join gemm
    k_y<<<nb, 256>>>(n);              // dinv + y = dinv*xw
    k_conv1<<<qb, 256>>>(e);
    k_fin1<<<nb, 256>>>(b1, Wmu, Wls, n);
    k_conv2<<<qb, 256>>>(e);
    k_fin2<<<nb, 256>>>(bmu, bls, (float*)d_out, n);
}

// round 7
// speedup vs baseline: 1.2954x; 1.0543x over previous
#include <cuda_runtime.h>
#include <cuda_bf16.h>
#include <math.h>

#define NN 100000
#define EE 3200000

// ---- scratch (device globals; allocation-free) ----
__device__ int    g_deg[NN];
__device__ float  g_dinv[NN];
__device__ int2   g_edge[EE];    // packed (src, dst)
__device__ float4 g_xw[NN];      // raw x @ W1
__device__ float4 g_y[NN];       // dinv * xw
__device__ float4 g_z[NN];       // dinv * (relu(conv1) @ [Wmu|Wls])
__device__ float4 g_acc1[NN];
__device__ float4 g_acc2[NN];
__device__ int    g_is64;

// ---- init: zero deg + accumulators; thread 0 detects int64 vs int32 ----
__global__ void k_init(const unsigned int* __restrict__ ei, int n) {
    int i = blockIdx.x * blockDim.x + threadIdx.x;
    if (i < n) {
        g_deg[i]  = 0;
        g_acc1[i] = make_float4(0.f, 0.f, 0.f, 0.f);
        g_acc2[i] = make_float4(0.f, 0.f, 0.f, 0.f);
    }
    if (blockIdx.x == 0 && threadIdx.x == 0) {
        int all0 = 1;
        #pragma unroll 1
        for (int k = 0; k < 64; ++k)
            if (ei[2 * k + 1] != 0u) { all0 = 0; break; }
        g_is64 = all0;   // int64 LE with ids < 2^31 => odd words all zero
    }
}

// ---- fused: edge decode+histogram blocks interleaved with gemm blocks ----
// Edge block: 2 edges/thread -> packed int2 + deg atomics (atomic-ALU bound).
// Gemm block: one warp per row of x @ W1 (DRAM bound).
// Interleave pattern hides the atomic kernel under the DRAM kernel.
__global__ void __launch_bounds__(256) k_fused(const float* __restrict__ x,
                                               const float* __restrict__ W1,
                                               const void* __restrict__ ei,
                                               int n, int e,
                                               int ebk, int gbk) {
    __shared__ float4 Ws[512];
    int b = blockIdx.x;
    int t = threadIdx.x;

    int edgeB, gemmB;   // role + role-local block id
    if (gbk == 2 * ebk) {
        int r = b % 3;
        if (r == 0) { edgeB = b / 3; gemmB = -1; }
        else        { edgeB = -1;    gemmB = (b / 3) * 2 + (r - 1); }
    } else {
        if (b < ebk) { edgeB = b; gemmB = -1; }
        else         { edgeB = -1; gemmB = b - ebk; }
    }

    if (edgeB >= 0) {
        // ---------------- edge work ----------------
        int i = edgeB * 256 + t;
        int npair = e >> 1;
        if (i < npair) {
            int s0, s1, d0, d1;
            if (g_is64) {
                const longlong2* ps = (const longlong2*)ei;
                const longlong2* pd = (const longlong2*)((const long long*)ei + e);
                longlong2 sv = __ldg(&ps[i]);
                longlong2 dv = __ldg(&pd[i]);
                s0 = (int)sv.x; s1 = (int)sv.y; d0 = (int)dv.x; d1 = (int)dv.y;
            } else {
                const int2* ps = (const int2*)ei;
                const int2* pd = (const int2*)((const int*)ei + e);
                int2 sv = __ldg(&ps[i]);
                int2 dv = __ldg(&pd[i]);
                s0 = sv.x; s1 = sv.y; d0 = dv.x; d1 = dv.y;
            }
            ((int4*)g_edge)[i] = make_int4(s0, d0, s1, d1);
            atomicAdd(&g_deg[d0], 1);
            atomicAdd(&g_deg[d1], 1);
        }
        if (i == 0 && (e & 1)) {       // odd tail (E even in practice)
            int s, d;
            if (g_is64) {
                const long long* p = (const long long*)ei;
                s = (int)p[e - 1]; d = (int)p[2 * (long long)e - 1];
            } else {
                const int* p = (const int*)ei;
                s = p[e - 1]; d = p[2 * e - 1];
            }
            g_edge[e - 1] = make_int2(s, d);
            atomicAdd(&g_deg[d], 1);
        }
    } else {
        // ---------------- gemm work ----------------
        const float4* W4 = (const float4*)W1;
        Ws[t]       = W4[t];
        Ws[t + 256] = W4[t + 256];
        __syncthreads();

        int warp = t >> 5, lane = t & 31;
        int row  = gemmB * 8 + warp;
        if (row >= n) return;

        const float4* xr = (const float4*)(x + (size_t)row * 512);
        float4 acc = make_float4(0.f, 0.f, 0.f, 0.f);
        #pragma unroll
        for (int i = 0; i < 4; ++i) {
            float4 xv = __ldg(&xr[i * 32 + lane]);
            int k = i * 128 + lane * 4;
            float4 w0 = Ws[k], w1 = Ws[k + 1], w2 = Ws[k + 2], w3 = Ws[k + 3];
            acc.x += xv.x * w0.x + xv.y * w1.x + xv.z * w2.x + xv.w * w3.x;
            acc.y += xv.x * w0.y + xv.y * w1.y + xv.z * w2.y + xv.w * w3.y;
            acc.z += xv.x * w0.z + xv.y * w1.z + xv.z * w2.z + xv.w * w3.z;
            acc.w += xv.x * w0.w + xv.y * w1.w + xv.z * w2.w + xv.w * w3.w;
        }
        #pragma unroll
        for (int off = 16; off; off >>= 1) {
            acc.x += __shfl_xor_sync(0xffffffffu, acc.x, off);
            acc.y += __shfl_xor_sync(0xffffffffu, acc.y, off);
            acc.z += __shfl_xor_sync(0xffffffffu, acc.z, off);
            acc.w += __shfl_xor_sync(0xffffffffu, acc.w, off);
        }
        if (lane == 0) g_xw[row] = acc;
    }
}

// ---- dinv = rsqrt(deg+1); y = dinv * xw ----
__global__ void k_y(int n) {
    int i = blockIdx.x * blockDim.x + threadIdx.x;
    if (i >= n) return;
    float di = rsqrtf((float)(g_deg[i] + 1));
    g_dinv[i] = di;
    float4 v = g_xw[i];
    g_y[i] = make_float4(di * v.x, di * v.y, di * v.z, di * v.w);
}

// ---- conv1 scatter: 4 edges/thread, 4 independent gathers + 4 REDs ----
__global__ void __launch_bounds__(256) k_conv1(int e) {
    int i = blockIdx.x * blockDim.x + threadIdx.x;
    int base = i * 4;
    if (base >= e) return;
    if (base + 3 < e) {
        int4 a = ((const int4*)g_edge)[i * 2];
        int4 b = ((const int4*)g_edge)[i * 2 + 1];
        float4 v0 = g_y[a.x];
        float4 v1 = g_y[a.z];
        float4 v2 = g_y[b.x];
        float4 v3 = g_y[b.z];
        atomicAdd(&g_acc1[a.y], v0);
        atomicAdd(&g_acc1[a.w], v1);
        atomicAdd(&g_acc1[b.y], v2);
        atomicAdd(&g_acc1[b.w], v3);
    } else {
        for (int j = base; j < e; ++j) {
            int2 ed = g_edge[j];
            atomicAdd(&g_acc1[ed.y], g_y[ed.x]);
        }
    }
}

// ---- finalize conv1: h = relu(di*(acc+y)+b1); z = di * (h @ [Wmu|Wls]) ----
__global__ void k_fin1(const float* __restrict__ b1,
                       const float* __restrict__ Wmu,
                       const float* __restrict__ Wls, int n) {
    int i = blockIdx.x * blockDim.x + threadIdx.x;
    if (i >= n) return;
    float di = g_dinv[i];
    float4 a = g_acc1[i];
    float4 y = g_y[i];
    float h0 = fmaxf(di * (a.x + y.x) + __ldg(&b1[0]), 0.f);
    float h1 = fmaxf(di * (a.y + y.y) + __ldg(&b1[1]), 0.f);
    float h2 = fmaxf(di * (a.z + y.z) + __ldg(&b1[2]), 0.f);
    float h3 = fmaxf(di * (a.w + y.w) + __ldg(&b1[3]), 0.f);
    float4 o;   // W_mu, W_ls: [4,2] row-major
    o.x = h0 * __ldg(&Wmu[0]) + h1 * __ldg(&Wmu[2]) + h2 * __ldg(&Wmu[4]) + h3 * __ldg(&Wmu[6]);
    o.y = h0 * __ldg(&Wmu[1]) + h1 * __ldg(&Wmu[3]) + h2 * __ldg(&Wmu[5]) + h3 * __ldg(&Wmu[7]);
    o.z = h0 * __ldg(&Wls[0]) + h1 * __ldg(&Wls[2]) + h2 * __ldg(&Wls[4]) + h3 * __ldg(&Wls[6]);
    o.w = h0 * __ldg(&Wls[1]) + h1 * __ldg(&Wls[3]) + h2 * __ldg(&Wls[5]) + h3 * __ldg(&Wls[7]);
    g_z[i] = make_float4(di * o.x, di * o.y, di * o.z, di * o.w);
}

// ---- conv2 scatter: 4 edges/thread ----
__global__ void __launch_bounds__(256) k_conv2(int e) {
    int i = blockIdx.x * blockDim.x + threadIdx.x;
    int base = i * 4;
    if (base >= e) return;
    if (base + 3 < e) {
        int4 a = ((const int4*)g_edge)[i * 2];
        int4 b = ((const int4*)g_edge)[i * 2 + 1];
        float4 v0 = g_z[a.x];
        float4 v1 = g_z[a.z];
        float4 v2 = g_z[b.x];
        float4 v3 = g_z[b.z];
        atomicAdd(&g_acc2[a.y], v0);
        atomicAdd(&g_acc2[a.w], v1);
        atomicAdd(&g_acc2[b.y], v2);
        atomicAdd(&g_acc2[b.w], v3);
    } else {
        for (int j = base; j < e; ++j) {
            int2 ed = g_edge[j];
            atomicAdd(&g_acc2[ed.y], g_z[ed.x]);
        }
    }
}

// ---- finalize conv2: out = di*(acc2+z) + bias ----
__global__ void k_fin2(const float* __restrict__ bmu,
                       const float* __restrict__ bls,
                       float* __restrict__ out, int n) {
    int i = blockIdx.x * blockDim.x + threadIdx.x;
    if (i >= n) return;
    float di = g_dinv[i];
    float4 a = g_acc2[i];
    float4 z = g_z[i];
    float2 mu, ls;
    mu.x = di * (a.x + z.x) + __ldg(&bmu[0]);
    mu.y = di * (a.y + z.y) + __ldg(&bmu[1]);
    ls.x = di * (a.z + z.z) + __ldg(&bls[0]);
    ls.y = di * (a.w + z.w) + __ldg(&bls[1]);
    ((float2*)out)[i] = mu;                       // mu [N,2]
    ((float2*)(out + 2 * (size_t)n))[i] = ls;     // logstd [N,2]
}

extern "C" void kernel_launch(void* const* d_in, const int* in_sizes, int n_in,
                              void* d_out, int out_size) {
    const float* x   = (const float*)d_in[0];
    const void*  ei  = d_in[1];
    const float* W1  = (const float*)d_in[2];
    const float* b1  = (const float*)d_in[3];
    const float* Wmu = (const float*)d_in[4];
    const float* bmu = (const float*)d_in[5];
    const float* Wls = (const float*)d_in[6];
    const float* bls = (const float*)d_in[7];

    int n = in_sizes[0] / 512;   // 100000
    int e = in_sizes[1] / 2;     // 3200000

    int nb  = (n + 255) / 256;
    int ebk = ((e >> 1) + 255) / 256;     // edge-pair blocks  (6250)
    int gbk = (n + 7) / 8;                // gemm blocks       (12500)
    int qb  = ((e + 3) / 4 + 255) / 256;  // conv edge-quad blocks

    k_init<<<nb, 256>>>((const unsigned int*)ei, n);
    k_fused<<<ebk + gbk, 256>>>(x, W1, ei, n, e, ebk, gbk);  // edges ∥ gemm
    k_y<<<nb, 256>>>(n);
    k_conv1<<<qb, 256>>>(e);
    k_fin1<<<nb, 256>>>(b1, Wmu, Wls, n);
    k_conv2<<<qb, 256>>>(e);
    k_fin2<<<nb, 256>>>(bmu, bls, (float*)d_out, n);
}